// round 7
// baseline (speedup 1.0000x reference)
#include <cuda_runtime.h>
#include <cuda_bf16.h>
#include <cstdint>

// ===========================================================================
// PerceiverAttentionCA — mma.sync tf32 path.
// R7: GEMM occupancy fix — 512 threads/CTA, 16 warps with 32x32 warp tiles
// (4 warps/SMSP instead of 2), same 128x128x32 CTA tile + fragment-layout
// smem staging + double buffering.
// ===========================================================================

#define B_SZ 2
#define N1 2048
#define N2 2048
#define DIM 3072
#define KV_DIM 2048
#define HEADS 16
#define DHEAD 128
#define INNER 2048

// ---------------- scratch (static device globals) ----------------
__device__ __align__(16) float g_xn  [(size_t)B_SZ * N1 * KV_DIM];
__device__ __align__(16) float g_ln  [(size_t)B_SZ * N2 * DIM];
__device__ __align__(16) float g_q   [(size_t)B_SZ * N2 * INNER];
__device__ __align__(16) float g_kv  [(size_t)B_SZ * N1 * 2 * INNER];
__device__ __align__(16) float g_s   [(size_t)B_SZ * HEADS * N2 * N1];
__device__ __align__(16) float g_at  [(size_t)B_SZ * N2 * INNER];
__device__ __align__(16) float g_wqT [(size_t)INNER * DIM];
__device__ __align__(16) float g_wkvT[(size_t)2 * INNER * KV_DIM];
__device__ __align__(16) float g_woT [(size_t)DIM * INNER];
__device__ __align__(16) float g_vt  [(size_t)B_SZ * INNER * N1];

__device__ __forceinline__ uint32_t f2tf32(float f) {
    uint32_t o; asm("cvt.rna.tf32.f32 %0, %1;" : "=r"(o) : "f"(f)); return o;
}

__device__ __forceinline__ void mma_tf32(float* d, const uint32_t* a,
                                         const uint32_t* b) {
    asm volatile(
        "mma.sync.aligned.m16n8k8.row.col.f32.tf32.tf32.f32 "
        "{%0,%1,%2,%3}, {%4,%5,%6,%7}, {%8,%9}, {%0,%1,%2,%3};"
        : "+f"(d[0]), "+f"(d[1]), "+f"(d[2]), "+f"(d[3])
        : "r"(a[0]), "r"(a[1]), "r"(a[2]), "r"(a[3]), "r"(b[0]), "r"(b[1]));
}

// ---------------------------------------------------------------------------
// SMEM fragment layout (identical to R6):
//  A: 32 tiles (8 m16-tiles x 4 k8-steps), tile = 32 lanes x 4 regs,
//     stride 132 floats -> fragment load = one LDS.128.
//  B: 64 tiles (16 n8-tiles x 4 k8-steps), tile = 32 lanes x 2 regs,
//     stride 68 floats  -> fragment load = one LDS.64.
// ---------------------------------------------------------------------------
#define A_TS 132
#define B_TS 68
#define A_STAGE (32 * A_TS)
#define B_STAGE (64 * B_TS)
#define STAGE_FLOATS (A_STAGE + B_STAGE)
#define GEMM_SMEM_BYTES (2 * STAGE_FLOATS * 4)

// C = alpha * A @ B^T ; A:[M,K] K-major, B:[N,K] K-major.
// grid = (N/128, M/128, batch); batch z -> (z/nheads, z%nheads) strides.
// 512 threads: 16 warps, warp tile 32x32 (2 m16-tiles x 4 n8-tiles).
__global__ void __launch_bounds__(512, 1) hmma_gemm(
    const float* __restrict__ A, const float* __restrict__ B,
    float* __restrict__ C,
    int K, int lda, int ldb, int ldc,
    long long hA, long long bA, long long hB, long long bB,
    long long hC, long long bC, int nheads, float alpha)
{
    extern __shared__ uint32_t smem[];
    const int tid = threadIdx.x;
    const int lid = tid & 31, wid = tid >> 5;
    const int wm = wid >> 2, wn = wid & 3;   // 4 x 4 warp grid

    const int z = blockIdx.z;
    const int bbz = z / nheads, hhz = z % nheads;
    A += (size_t)bbz * bA + (size_t)hhz * hA;
    B += (size_t)bbz * bB + (size_t)hhz * hB;
    C += (size_t)bbz * bC + (size_t)hhz * hC;
    const int bm = blockIdx.y << 7, bn = blockIdx.x << 7;

    // ---- staging geometry: 512 threads, each stages 2 float4 of A and B ----
    const int r0 = tid >> 3;           // 0..63
    const int kq = tid & 7;            // 0..7 (k-quad: 4 consecutive k)
    const int ks_w = kq >> 1;          // k8-step of this quad
    const int rka = (kq & 1) << 1;     // A reg offset from (k&4)
    const int rkb = kq & 1;            // B reg offset from (k&4)

    int offA[2], offB[2];
    #pragma unroll
    for (int i = 0; i < 2; i++) {
        int row = r0 + (i << 6);       // rows r0, r0+64
        offA[i] = (((row >> 4) << 2) + ks_w) * A_TS +
                  ((row & 7) << 4) + ((row >> 3) & 1) + rka;
        offB[i] = (((row >> 3) << 2) + ks_w) * B_TS +
                  ((row & 7) << 3) + rkb;
    }

    const float* Aldg = A + (size_t)(bm + r0) * lda + (kq << 2);
    const float* Bldg = B + (size_t)(bn + r0) * ldb + (kq << 2);

    float acc[2][4][4];
    #pragma unroll
    for (int i = 0; i < 2; i++)
        #pragma unroll
        for (int j = 0; j < 4; j++)
            #pragma unroll
            for (int r = 0; r < 4; r++) acc[i][j][r] = 0.f;

    const int S = K >> 5;
    float4 av[2], bv[2];

    // prologue: stage 0
    #pragma unroll
    for (int i = 0; i < 2; i++) {
        av[i] = *(const float4*)(Aldg + (size_t)(i << 6) * lda);
        bv[i] = *(const float4*)(Bldg + (size_t)(i << 6) * ldb);
    }
    {
        uint32_t* sA = smem;
        uint32_t* sB = smem + A_STAGE;
        #pragma unroll
        for (int i = 0; i < 2; i++) {
            sA[offA[i] + 0]  = f2tf32(av[i].x);
            sA[offA[i] + 4]  = f2tf32(av[i].y);
            sA[offA[i] + 8]  = f2tf32(av[i].z);
            sA[offA[i] + 12] = f2tf32(av[i].w);
            sB[offB[i] + 0]  = f2tf32(bv[i].x);
            sB[offB[i] + 2]  = f2tf32(bv[i].y);
            sB[offB[i] + 4]  = f2tf32(bv[i].z);
            sB[offB[i] + 6]  = f2tf32(bv[i].w);
        }
    }
    __syncthreads();

    for (int s = 0; s < S; s++) {
        const int b = s & 1;
        if (s + 1 < S) {
            const int k0 = (s + 1) << 5;   // contiguous K offset
            #pragma unroll
            for (int i = 0; i < 2; i++) {
                av[i] = *(const float4*)(Aldg + k0 + (size_t)(i << 6) * lda);
                bv[i] = *(const float4*)(Bldg + k0 + (size_t)(i << 6) * ldb);
            }
        }

        // compute on buffer b
        {
            const uint32_t* sA = smem + b * STAGE_FLOATS;
            const uint32_t* sB = sA + A_STAGE;
            #pragma unroll
            for (int ks = 0; ks < 4; ks++) {
                uint32_t Af[2][4], Bf[4][2];
                #pragma unroll
                for (int mt = 0; mt < 2; mt++)
                    *(uint4*)Af[mt] = *(const uint4*)
                        &sA[((((wm << 1) + mt) << 2) + ks) * A_TS + (lid << 2)];
                #pragma unroll
                for (int nt = 0; nt < 4; nt++)
                    *(uint2*)Bf[nt] = *(const uint2*)
                        &sB[((((wn << 2) + nt) << 2) + ks) * B_TS + (lid << 1)];
                #pragma unroll
                for (int mt = 0; mt < 2; mt++)
                    #pragma unroll
                    for (int nt = 0; nt < 4; nt++)
                        mma_tf32(acc[mt][nt], Af[mt], Bf[nt]);
            }
        }

        if (s + 1 < S) {
            __syncthreads();
            uint32_t* sA = smem + (b ^ 1) * STAGE_FLOATS;
            uint32_t* sB = sA + A_STAGE;
            #pragma unroll
            for (int i = 0; i < 2; i++) {
                sA[offA[i] + 0]  = f2tf32(av[i].x);
                sA[offA[i] + 4]  = f2tf32(av[i].y);
                sA[offA[i] + 8]  = f2tf32(av[i].z);
                sA[offA[i] + 12] = f2tf32(av[i].w);
                sB[offB[i] + 0]  = f2tf32(bv[i].x);
                sB[offB[i] + 2]  = f2tf32(bv[i].y);
                sB[offB[i] + 4]  = f2tf32(bv[i].z);
                sB[offB[i] + 6]  = f2tf32(bv[i].w);
            }
            __syncthreads();
        }
    }

    // epilogue: warp (wm, wn) owns rows [wm*32, +32), cols [wn*32, +32)
    #pragma unroll
    for (int mt = 0; mt < 2; mt++) {
        #pragma unroll
        for (int nt = 0; nt < 4; nt++) {
            int r = bm + (wm << 5) + (mt << 4) + (lid >> 2);
            int c = bn + (wn << 5) + (nt << 3) + ((lid & 3) << 1);
            float2 v0, v1;
            v0.x = acc[mt][nt][0] * alpha; v0.y = acc[mt][nt][1] * alpha;
            v1.x = acc[mt][nt][2] * alpha; v1.y = acc[mt][nt][3] * alpha;
            *(float2*)(C + (size_t)r * ldc + c)       = v0;
            *(float2*)(C + (size_t)(r + 8) * ldc + c) = v1;
        }
    }
}

// ---------------------------------------------------------------------------
// LayerNorm
// ---------------------------------------------------------------------------
__global__ void __launch_bounds__(256) ln_kernel(
    const float* __restrict__ x, const float* __restrict__ gam,
    const float* __restrict__ bet, float* __restrict__ out, int cols)
{
    const int row = blockIdx.x;
    const float* xr = x + (size_t)row * cols;
    float* orow = out + (size_t)row * cols;

    float s = 0.f, s2 = 0.f;
    for (int i = threadIdx.x; i < cols; i += blockDim.x) {
        float v = xr[i]; s += v; s2 += v * v;
    }
    __shared__ float sm0[8], sm1[8];
    #pragma unroll
    for (int o = 16; o > 0; o >>= 1) {
        s  += __shfl_down_sync(0xffffffffu, s,  o);
        s2 += __shfl_down_sync(0xffffffffu, s2, o);
    }
    int w = threadIdx.x >> 5, l = threadIdx.x & 31;
    if (l == 0) { sm0[w] = s; sm1[w] = s2; }
    __syncthreads();
    if (threadIdx.x == 0) {
        float ts = 0.f, t2 = 0.f;
        #pragma unroll
        for (int i = 0; i < 8; i++) { ts += sm0[i]; t2 += sm1[i]; }
        float mu  = ts / (float)cols;
        float var = t2 / (float)cols - mu * mu;
        sm0[0] = mu; sm1[0] = rsqrtf(var + 1e-5f);
    }
    __syncthreads();
    float mu = sm0[0], rs = sm1[0];
    for (int i = threadIdx.x; i < cols; i += blockDim.x) {
        float v = xr[i];
        orow[i] = (v - mu) * rs * gam[i] + bet[i];
    }
}

// ---------------------------------------------------------------------------
// Batched 32x32 tiled transpose
// ---------------------------------------------------------------------------
__global__ void transpose_kernel(
    const float* __restrict__ in, float* __restrict__ out,
    int ldi, int ldo,
    long long hI, long long bI, long long hO, long long bO, int nheads)
{
    __shared__ float t[32][33];
    const int z = blockIdx.z;
    const int bb = z / nheads, hh = z % nheads;
    in  += (size_t)bb * bI + (size_t)hh * hI;
    out += (size_t)bb * bO + (size_t)hh * hO;
    int x = blockIdx.x * 32 + threadIdx.x;
    int y = blockIdx.y * 32 + threadIdx.y;
    #pragma unroll
    for (int j = 0; j < 32; j += 8)
        t[threadIdx.y + j][threadIdx.x] = in[(size_t)(y + j) * ldi + x];
    __syncthreads();
    int x2 = blockIdx.y * 32 + threadIdx.x;
    int y2 = blockIdx.x * 32 + threadIdx.y;
    #pragma unroll
    for (int j = 0; j < 32; j += 8)
        out[(size_t)(y2 + j) * ldo + x2] = t[threadIdx.x][threadIdx.y + j];
}

// ---------------------------------------------------------------------------
// Row softmax over 2048 cols
// ---------------------------------------------------------------------------
__global__ void __launch_bounds__(256) softmax_kernel(float* __restrict__ S)
{
    float* p = S + (size_t)blockIdx.x * 2048;
    const int tid = threadIdx.x;
    float v[8];
    float m = -1e30f;
    #pragma unroll
    for (int i = 0; i < 8; i++) { v[i] = p[i * 256 + tid]; m = fmaxf(m, v[i]); }
    __shared__ float sm[8];
    #pragma unroll
    for (int o = 16; o > 0; o >>= 1)
        m = fmaxf(m, __shfl_xor_sync(0xffffffffu, m, o));
    int w = tid >> 5;
    if ((tid & 31) == 0) sm[w] = m;
    __syncthreads();
    if (tid < 8) {
        float t = sm[tid];
        #pragma unroll
        for (int o = 4; o > 0; o >>= 1)
            t = fmaxf(t, __shfl_xor_sync(0xffu, t, o));
        sm[tid] = t;
    }
    __syncthreads();
    m = sm[0];
    float sum = 0.f;
    #pragma unroll
    for (int i = 0; i < 8; i++) { v[i] = __expf(v[i] - m); sum += v[i]; }
    __shared__ float ss[8];
    #pragma unroll
    for (int o = 16; o > 0; o >>= 1)
        sum += __shfl_xor_sync(0xffffffffu, sum, o);
    if ((tid & 31) == 0) ss[w] = sum;
    __syncthreads();
    if (tid < 8) {
        float t = ss[tid];
        #pragma unroll
        for (int o = 4; o > 0; o >>= 1)
            t += __shfl_xor_sync(0xffu, t, o);
        ss[tid] = t;
    }
    __syncthreads();
    float inv = 1.0f / ss[0];
    #pragma unroll
    for (int i = 0; i < 8; i++) p[i * 256 + tid] = v[i] * inv;
}

// ---------------------------------------------------------------------------
extern "C" void kernel_launch(void* const* d_in, const int* in_sizes, int n_in,
                              void* d_out, int out_size)
{
    const float* x      = (const float*)d_in[0];
    const float* lat    = (const float*)d_in[1];
    const float* w_q    = (const float*)d_in[2];
    const float* w_kv   = (const float*)d_in[3];
    const float* w_out  = (const float*)d_in[4];
    const float* ln1_g  = (const float*)d_in[5];
    const float* ln1_b  = (const float*)d_in[6];
    const float* ln2_g  = (const float*)d_in[7];
    const float* ln2_b  = (const float*)d_in[8];
    float* out = (float*)d_out;

    float *xn, *ln, *q, *kv, *S, *att, *wqT, *wkvT, *woT, *vt;
    cudaGetSymbolAddress((void**)&xn,   g_xn);
    cudaGetSymbolAddress((void**)&ln,   g_ln);
    cudaGetSymbolAddress((void**)&q,    g_q);
    cudaGetSymbolAddress((void**)&kv,   g_kv);
    cudaGetSymbolAddress((void**)&S,    g_s);
    cudaGetSymbolAddress((void**)&att,  g_at);
    cudaGetSymbolAddress((void**)&wqT,  g_wqT);
    cudaGetSymbolAddress((void**)&wkvT, g_wkvT);
    cudaGetSymbolAddress((void**)&woT,  g_woT);
    cudaGetSymbolAddress((void**)&vt,   g_vt);

    cudaFuncSetAttribute(hmma_gemm, cudaFuncAttributeMaxDynamicSharedMemorySize,
                         GEMM_SMEM_BYTES);

    const dim3 tb(32, 8);

    // LayerNorms
    ln_kernel<<<B_SZ * N1, 256>>>(x,   ln1_g, ln1_b, xn, KV_DIM);
    ln_kernel<<<B_SZ * N2, 256>>>(lat, ln2_g, ln2_b, ln, DIM);

    // weight transposes (K-major B operands)
    transpose_kernel<<<dim3(INNER / 32, DIM / 32, 1), tb>>>(
        w_q, wqT, INNER, DIM, 0, 0, 0, 0, 1);
    transpose_kernel<<<dim3((2 * INNER) / 32, KV_DIM / 32, 1), tb>>>(
        w_kv, wkvT, 2 * INNER, KV_DIM, 0, 0, 0, 0, 1);
    transpose_kernel<<<dim3(DIM / 32, INNER / 32, 1), tb>>>(
        w_out, woT, DIM, INNER, 0, 0, 0, 0, 1);

    // q = ln @ w_q  : M=4096 N=2048 K=3072
    hmma_gemm<<<dim3(INNER / 128, (B_SZ * N2) / 128, 1), 512, GEMM_SMEM_BYTES>>>(
        ln, wqT, q, DIM, DIM, DIM, INNER,
        0, 0, 0, 0, 0, 0, 1, 1.0f);

    // kv = xn @ w_kv : M=4096 N=4096 K=2048
    hmma_gemm<<<dim3((2 * INNER) / 128, (B_SZ * N1) / 128, 1), 512, GEMM_SMEM_BYTES>>>(
        xn, wkvT, kv, KV_DIM, KV_DIM, KV_DIM, 2 * INNER,
        0, 0, 0, 0, 0, 0, 1, 1.0f);

    // v^T per (b,h): vt[b][h][d][n1]
    transpose_kernel<<<dim3(DHEAD / 32, N1 / 32, B_SZ * HEADS), tb>>>(
        kv + INNER, vt, 2 * INNER, N1,
        /*hI*/ DHEAD, /*bI*/ (long long)N1 * 2 * INNER,
        /*hO*/ (long long)DHEAD * N1, /*bO*/ (long long)INNER * N1, HEADS);

    // S = alpha * q @ k^T per (b,h): M=2048 N=2048 K=128
    hmma_gemm<<<dim3(N1 / 128, N2 / 128, B_SZ * HEADS), 512, GEMM_SMEM_BYTES>>>(
        q, kv, S, DHEAD, INNER, 2 * INNER, N1,
        /*hA*/ DHEAD, /*bA*/ (long long)N2 * INNER,
        /*hB*/ DHEAD, /*bB*/ (long long)N1 * 2 * INNER,
        /*hC*/ (long long)N2 * N1, /*bC*/ (long long)HEADS * N2 * N1,
        HEADS, 0.08838834764831845f);

    // softmax
    softmax_kernel<<<B_SZ * HEADS * N2, 256>>>(S);

    // att = P @ v per (b,h): M=2048 N=128 K=2048  (B = vt, K-major)
    hmma_gemm<<<dim3(1, N2 / 128, B_SZ * HEADS), 512, GEMM_SMEM_BYTES>>>(
        S, vt, att, N1, N1, N1, INNER,
        /*hA*/ (long long)N2 * N1, /*bA*/ (long long)HEADS * N2 * N1,
        /*hB*/ (long long)DHEAD * N1, /*bB*/ (long long)INNER * N1,
        /*hC*/ DHEAD, /*bC*/ (long long)N2 * INNER,
        HEADS, 1.0f);

    // out = att @ w_out : M=4096 N=3072 K=2048
    hmma_gemm<<<dim3(DIM / 128, (B_SZ * N2) / 128, 1), 512, GEMM_SMEM_BYTES>>>(
        att, woT, out, INNER, INNER, INNER, DIM,
        0, 0, 0, 0, 0, 0, 1, 1.0f);
}

// round 12
// speedup vs baseline: 1.4222x; 1.4222x over previous
#include <cuda_runtime.h>
#include <cuda_fp16.h>
#include <cstdint>

// ===========================================================================
// PerceiverAttentionCA — fp16 mma.sync (m16n8k16) + ldmatrix + cp.async.
// R12: identical to R10/R11 (broker timeouts — resubmit for evidence).
// Fix under test: k-step folded into 16B-unit index BEFORE swizzle.
// ===========================================================================

#define B_SZ 2
#define N1 2048
#define N2 2048
#define DIM 3072
#define KV_DIM 2048
#define HEADS 16
#define DHEAD 128
#define INNER 2048

// ---------------- scratch (static device globals) ----------------
__device__ __align__(16) __half g_xn  [(size_t)B_SZ * N1 * KV_DIM];
__device__ __align__(16) __half g_ln  [(size_t)B_SZ * N2 * DIM];
__device__ __align__(16) __half g_q   [(size_t)B_SZ * N2 * INNER];
__device__ __align__(16) __half g_kv  [(size_t)B_SZ * N1 * 2 * INNER];
__device__ __align__(16) float  g_s   [(size_t)B_SZ * HEADS * N2 * N1];
__device__ __align__(16) __half g_p   [(size_t)B_SZ * HEADS * N2 * N1];
__device__ __align__(16) __half g_at  [(size_t)B_SZ * N2 * INNER];
__device__ __align__(16) __half g_wqT [(size_t)INNER * DIM];
__device__ __align__(16) __half g_wkvT[(size_t)2 * INNER * KV_DIM];
__device__ __align__(16) __half g_woT [(size_t)DIM * INNER];
__device__ __align__(16) __half g_vt  [(size_t)B_SZ * INNER * N1];

__device__ __forceinline__ uint32_t smem_u32(const void* p) {
    uint32_t a;
    asm("{ .reg .u64 t; cvta.to.shared.u64 t, %1; cvt.u32.u64 %0, t; }"
        : "=r"(a) : "l"(p));
    return a;
}

#define CP_ASYNC16(dst_u32, src_ptr) \
    asm volatile("cp.async.ca.shared.global [%0], [%1], 16;" \
                 :: "r"(dst_u32), "l"(src_ptr))
#define CP_COMMIT() asm volatile("cp.async.commit_group;")
#define CP_WAIT2()  asm volatile("cp.async.wait_group 2;")

__device__ __forceinline__ void ldsm_x4(uint32_t* r, uint32_t addr) {
    asm volatile("ldmatrix.sync.aligned.m8n8.x4.shared.b16 {%0,%1,%2,%3}, [%4];"
                 : "=r"(r[0]), "=r"(r[1]), "=r"(r[2]), "=r"(r[3]) : "r"(addr));
}
__device__ __forceinline__ void ldsm_x2(uint32_t* r, uint32_t addr) {
    asm volatile("ldmatrix.sync.aligned.m8n8.x2.shared.b16 {%0,%1}, [%2];"
                 : "=r"(r[0]), "=r"(r[1]) : "r"(addr));
}
__device__ __forceinline__ void mma_f16(float* d, const uint32_t* a,
                                        const uint32_t* b) {
    asm volatile(
        "mma.sync.aligned.m16n8k16.row.col.f32.f16.f16.f32 "
        "{%0,%1,%2,%3}, {%4,%5,%6,%7}, {%8,%9}, {%0,%1,%2,%3};"
        : "+f"(d[0]), "+f"(d[1]), "+f"(d[2]), "+f"(d[3])
        : "r"(a[0]), "r"(a[1]), "r"(a[2]), "r"(a[3]), "r"(b[0]), "r"(b[1]));
}

// smem tile: 128 rows x 32 halves (64B) per operand; unit = 16B (8 halves).
// swizzled byte offset for (row, unit); unit MUST be in 0..3 (pre-swizzle).
__device__ __forceinline__ uint32_t swz(int row, int u) {
    return (uint32_t)(row * 64 + ((u ^ ((row >> 1) & 3)) << 4));
}

#define STAGE_BYTES 16384          // A 8KB + B 8KB
#define GEMM_SMEM_BYTES (4 * STAGE_BYTES)

template <typename OutT>
__device__ __forceinline__ void store2(OutT* p, float x, float y);
template <>
__device__ __forceinline__ void store2<float>(float* p, float x, float y) {
    *(float2*)p = make_float2(x, y);
}
template <>
__device__ __forceinline__ void store2<__half>(__half* p, float x, float y) {
    *(__half2*)p = __floats2half2_rn(x, y);
}

// C = alpha * A @ B^T ; A:[M,K] K-major half, B:[N,K] K-major half.
// grid = (N/128, M/128, batch); batch z -> (z/nheads, z%nheads) strides.
// 256 threads, 8 warps: warp grid 2(m) x 4(n), warp tile 64x32.
template <typename OutT>
__global__ void __launch_bounds__(256, 2) hgemm(
    const __half* __restrict__ A, const __half* __restrict__ B,
    OutT* __restrict__ C,
    int K, int lda, int ldb, int ldc,
    long long hA, long long bA, long long hB, long long bB,
    long long hC, long long bC, int nheads, float alpha)
{
    extern __shared__ char smem[];
    const uint32_t sbase = smem_u32(smem);
    const int tid = threadIdx.x;
    const int lid = tid & 31, wid = tid >> 5;
    const int wm = wid >> 2, wn = wid & 3;

    const int z = blockIdx.z;
    const int bbz = z / nheads, hhz = z % nheads;
    A += (size_t)bbz * bA + (size_t)hhz * hA;
    B += (size_t)bbz * bB + (size_t)hhz * hB;
    C += (size_t)bbz * bC + (size_t)hhz * hC;
    const int bm = blockIdx.y << 7, bn = blockIdx.x << 7;

    // staging: thread -> (row 0..127, kb 0..1); 2x16B per operand per stage
    const int row = tid & 127;
    const int kb  = tid >> 7;
    const __half* srcA = A + (size_t)(bm + row) * lda + (kb << 4);
    const __half* srcB = B + (size_t)(bn + row) * ldb + (kb << 4);
    const uint32_t dA0 = swz(row, kb * 2);
    const uint32_t dA1 = swz(row, kb * 2 + 1);

    const int S = K >> 5;

    // prologue: stages 0..2
    #pragma unroll
    for (int st = 0; st < 3; st++) {
        if (st < S) {
            const uint32_t d = sbase + (st & 3) * STAGE_BYTES;
            const __half* a = srcA + (size_t)st * 32;
            const __half* b = srcB + (size_t)st * 32;
            CP_ASYNC16(d + dA0, a);
            CP_ASYNC16(d + dA1, a + 8);
            CP_ASYNC16(d + 8192 + dA0, b);
            CP_ASYNC16(d + 8192 + dA1, b + 8);
        }
        CP_COMMIT();
    }

    float acc[4][4][4];
    #pragma unroll
    for (int i = 0; i < 4; i++)
        #pragma unroll
        for (int j = 0; j < 4; j++)
            #pragma unroll
            for (int r = 0; r < 4; r++) acc[i][j][r] = 0.f;

    // fragment smem offsets, one per k16-step (unit folded in pre-swizzle)
    uint32_t offFA0[4], offFA1[4], offFB0[4], offFB1[4];
    {
        const int ua = lid >> 4;          // A unit-within-pair
        const int ub = (lid >> 3) & 1;    // B unit-within-pair
        #pragma unroll
        for (int mt = 0; mt < 4; mt++) {
            int r = (wm << 6) + (mt << 4) + (((lid >> 3) & 1) << 3) + (lid & 7);
            offFA0[mt] = swz(r, 0 + ua);      // ks=0 -> units 0/1
            offFA1[mt] = swz(r, 2 + ua);      // ks=1 -> units 2/3
        }
        #pragma unroll
        for (int nt = 0; nt < 4; nt++) {
            int r = (wn << 5) + (nt << 3) + (lid & 7);
            offFB0[nt] = swz(r, 0 + ub);
            offFB1[nt] = swz(r, 2 + ub);
        }
    }

    for (int s = 0; s < S; s++) {
        CP_WAIT2();
        __syncthreads();
        if (s + 3 < S) {
            const int st = s + 3;
            const uint32_t d = sbase + (st & 3) * STAGE_BYTES;
            const __half* a = srcA + (size_t)st * 32;
            const __half* b = srcB + (size_t)st * 32;
            CP_ASYNC16(d + dA0, a);
            CP_ASYNC16(d + dA1, a + 8);
            CP_ASYNC16(d + 8192 + dA0, b);
            CP_ASYNC16(d + 8192 + dA1, b + 8);
        }
        CP_COMMIT();

        const uint32_t sA = sbase + (s & 3) * STAGE_BYTES;
        const uint32_t sB = sA + 8192;
        #pragma unroll
        for (int ks = 0; ks < 2; ks++) {
            uint32_t Af[4][4], Bf[4][2];
            #pragma unroll
            for (int mt = 0; mt < 4; mt++)
                ldsm_x4(Af[mt], sA + (ks ? offFA1[mt] : offFA0[mt]));
            #pragma unroll
            for (int nt = 0; nt < 4; nt++)
                ldsm_x2(Bf[nt], sB + (ks ? offFB1[nt] : offFB0[nt]));
            #pragma unroll
            for (int mt = 0; mt < 4; mt++)
                #pragma unroll
                for (int nt = 0; nt < 4; nt++)
                    mma_f16(acc[mt][nt], Af[mt], Bf[nt]);
        }
    }

    // epilogue: warp (wm,wn) owns rows [wm*64,+64), cols [wn*32,+32)
    #pragma unroll
    for (int mt = 0; mt < 4; mt++) {
        #pragma unroll
        for (int nt = 0; nt < 4; nt++) {
            int r = bm + (wm << 6) + (mt << 4) + (lid >> 2);
            int c = bn + (wn << 5) + (nt << 3) + ((lid & 3) << 1);
            store2<OutT>(C + (size_t)r * ldc + c,
                         acc[mt][nt][0] * alpha, acc[mt][nt][1] * alpha);
            store2<OutT>(C + (size_t)(r + 8) * ldc + c,
                         acc[mt][nt][2] * alpha, acc[mt][nt][3] * alpha);
        }
    }
}

// ---------------------------------------------------------------------------
// LayerNorm: fp32 in, fp16 out
// ---------------------------------------------------------------------------
__global__ void __launch_bounds__(256) ln_kernel(
    const float* __restrict__ x, const float* __restrict__ gam,
    const float* __restrict__ bet, __half* __restrict__ out, int cols)
{
    const int row = blockIdx.x;
    const float* xr = x + (size_t)row * cols;
    __half* orow = out + (size_t)row * cols;

    float s = 0.f, s2 = 0.f;
    for (int i = threadIdx.x; i < cols; i += blockDim.x) {
        float v = xr[i]; s += v; s2 += v * v;
    }
    __shared__ float sm0[8], sm1[8];
    #pragma unroll
    for (int o = 16; o > 0; o >>= 1) {
        s  += __shfl_down_sync(0xffffffffu, s,  o);
        s2 += __shfl_down_sync(0xffffffffu, s2, o);
    }
    int w = threadIdx.x >> 5, l = threadIdx.x & 31;
    if (l == 0) { sm0[w] = s; sm1[w] = s2; }
    __syncthreads();
    if (threadIdx.x == 0) {
        float ts = 0.f, t2 = 0.f;
        #pragma unroll
        for (int i = 0; i < 8; i++) { ts += sm0[i]; t2 += sm1[i]; }
        float mu  = ts / (float)cols;
        float var = t2 / (float)cols - mu * mu;
        sm0[0] = mu; sm1[0] = rsqrtf(var + 1e-5f);
    }
    __syncthreads();
    float mu = sm0[0], rs = sm1[0];
    for (int i = threadIdx.x; i < cols; i += blockDim.x) {
        float v = xr[i];
        orow[i] = __float2half((v - mu) * rs * gam[i] + bet[i]);
    }
}

// ---------------------------------------------------------------------------
// Batched 32x32 tiled transpose: Tin in -> half out
// ---------------------------------------------------------------------------
template <typename Tin>
__global__ void transpose_kernel(
    const Tin* __restrict__ in, __half* __restrict__ out,
    int ldi, int ldo,
    long long hI, long long bI, long long hO, long long bO, int nheads)
{
    __shared__ __half t[32][34];
    const int z = blockIdx.z;
    const int bb = z / nheads, hh = z % nheads;
    in  += (size_t)bb * bI + (size_t)hh * hI;
    out += (size_t)bb * bO + (size_t)hh * hO;
    int x = blockIdx.x * 32 + threadIdx.x;
    int y = blockIdx.y * 32 + threadIdx.y;
    #pragma unroll
    for (int j = 0; j < 32; j += 8)
        t[threadIdx.y + j][threadIdx.x] =
            __float2half((float)in[(size_t)(y + j) * ldi + x]);
    __syncthreads();
    int x2 = blockIdx.y * 32 + threadIdx.x;
    int y2 = blockIdx.x * 32 + threadIdx.y;
    #pragma unroll
    for (int j = 0; j < 32; j += 8)
        out[(size_t)(y2 + j) * ldo + x2] = t[threadIdx.x][threadIdx.y + j];
}

// ---------------------------------------------------------------------------
// Row softmax over 2048 cols: fp32 S in, fp16 P out
// ---------------------------------------------------------------------------
__global__ void __launch_bounds__(256) softmax_kernel(
    const float* __restrict__ S, __half* __restrict__ P)
{
    const float* p = S + (size_t)blockIdx.x * 2048;
    __half* po = P + (size_t)blockIdx.x * 2048;
    const int tid = threadIdx.x;
    float v[8];
    float m = -1e30f;
    #pragma unroll
    for (int i = 0; i < 8; i++) { v[i] = p[i * 256 + tid]; m = fmaxf(m, v[i]); }
    __shared__ float sm[8];
    #pragma unroll
    for (int o = 16; o > 0; o >>= 1)
        m = fmaxf(m, __shfl_xor_sync(0xffffffffu, m, o));
    int w = tid >> 5;
    if ((tid & 31) == 0) sm[w] = m;
    __syncthreads();
    if (tid < 8) {
        float t = sm[tid];
        #pragma unroll
        for (int o = 4; o > 0; o >>= 1)
            t = fmaxf(t, __shfl_xor_sync(0xffu, t, o));
        sm[tid] = t;
    }
    __syncthreads();
    m = sm[0];
    float sum = 0.f;
    #pragma unroll
    for (int i = 0; i < 8; i++) { v[i] = __expf(v[i] - m); sum += v[i]; }
    __shared__ float ss[8];
    #pragma unroll
    for (int o = 16; o > 0; o >>= 1)
        sum += __shfl_xor_sync(0xffffffffu, sum, o);
    if ((tid & 31) == 0) ss[w] = sum;
    __syncthreads();
    if (tid < 8) {
        float t = ss[tid];
        #pragma unroll
        for (int o = 4; o > 0; o >>= 1)
            t += __shfl_xor_sync(0xffu, t, o);
        ss[tid] = t;
    }
    __syncthreads();
    float inv = 1.0f / ss[0];
    #pragma unroll
    for (int i = 0; i < 8; i++)
        po[i * 256 + tid] = __float2half(v[i] * inv);
}

// ---------------------------------------------------------------------------
extern "C" void kernel_launch(void* const* d_in, const int* in_sizes, int n_in,
                              void* d_out, int out_size)
{
    const float* x      = (const float*)d_in[0];
    const float* lat    = (const float*)d_in[1];
    const float* w_q    = (const float*)d_in[2];
    const float* w_kv   = (const float*)d_in[3];
    const float* w_out  = (const float*)d_in[4];
    const float* ln1_g  = (const float*)d_in[5];
    const float* ln1_b  = (const float*)d_in[6];
    const float* ln2_g  = (const float*)d_in[7];
    const float* ln2_b  = (const float*)d_in[8];
    float* out = (float*)d_out;

    __half *xn, *ln, *q, *kv, *P, *att, *wqT, *wkvT, *woT, *vt;
    float* S;
    cudaGetSymbolAddress((void**)&xn,   g_xn);
    cudaGetSymbolAddress((void**)&ln,   g_ln);
    cudaGetSymbolAddress((void**)&q,    g_q);
    cudaGetSymbolAddress((void**)&kv,   g_kv);
    cudaGetSymbolAddress((void**)&S,    g_s);
    cudaGetSymbolAddress((void**)&P,    g_p);
    cudaGetSymbolAddress((void**)&att,  g_at);
    cudaGetSymbolAddress((void**)&wqT,  g_wqT);
    cudaGetSymbolAddress((void**)&wkvT, g_wkvT);
    cudaGetSymbolAddress((void**)&woT,  g_woT);
    cudaGetSymbolAddress((void**)&vt,   g_vt);

    cudaFuncSetAttribute(hgemm<float>,
        cudaFuncAttributeMaxDynamicSharedMemorySize, GEMM_SMEM_BYTES);
    cudaFuncSetAttribute(hgemm<__half>,
        cudaFuncAttributeMaxDynamicSharedMemorySize, GEMM_SMEM_BYTES);

    const dim3 tb(32, 8);

    // LayerNorms (fp32 -> fp16)
    ln_kernel<<<B_SZ * N1, 256>>>(x,   ln1_g, ln1_b, xn, KV_DIM);
    ln_kernel<<<B_SZ * N2, 256>>>(lat, ln2_g, ln2_b, ln, DIM);

    // weight transposes (fp32 -> fp16, K-major)
    transpose_kernel<float><<<dim3(INNER / 32, DIM / 32, 1), tb>>>(
        w_q, wqT, INNER, DIM, 0, 0, 0, 0, 1);
    transpose_kernel<float><<<dim3((2 * INNER) / 32, KV_DIM / 32, 1), tb>>>(
        w_kv, wkvT, 2 * INNER, KV_DIM, 0, 0, 0, 0, 1);
    transpose_kernel<float><<<dim3(DIM / 32, INNER / 32, 1), tb>>>(
        w_out, woT, DIM, INNER, 0, 0, 0, 0, 1);

    // q = ln @ w_q : M=4096 N=2048 K=3072 (half out)
    hgemm<__half><<<dim3(INNER / 128, (B_SZ * N2) / 128, 1), 256,
                    GEMM_SMEM_BYTES>>>(
        ln, wqT, q, DIM, DIM, DIM, INNER,
        0, 0, 0, 0, 0, 0, 1, 1.0f);

    // kv = xn @ w_kv : M=4096 N=4096 K=2048 (half out)
    hgemm<__half><<<dim3((2 * INNER) / 128, (B_SZ * N1) / 128, 1), 256,
                    GEMM_SMEM_BYTES>>>(
        xn, wkvT, kv, KV_DIM, KV_DIM, KV_DIM, 2 * INNER,
        0, 0, 0, 0, 0, 0, 1, 1.0f);

    // v^T per (b,h): vt[b][h][d][n1] (half -> half)
    transpose_kernel<__half><<<dim3(DHEAD / 32, N1 / 32, B_SZ * HEADS), tb>>>(
        kv + INNER, vt, 2 * INNER, N1,
        /*hI*/ DHEAD, /*bI*/ (long long)N1 * 2 * INNER,
        /*hO*/ (long long)DHEAD * N1, /*bO*/ (long long)INNER * N1, HEADS);

    // S = alpha * q @ k^T per (b,h): M=2048 N=2048 K=128 (float out)
    hgemm<float><<<dim3(N1 / 128, N2 / 128, B_SZ * HEADS), 256,
                   GEMM_SMEM_BYTES>>>(
        q, kv, S, DHEAD, INNER, 2 * INNER, N1,
        /*hA*/ DHEAD, /*bA*/ (long long)N2 * INNER,
        /*hB*/ DHEAD, /*bB*/ (long long)N1 * 2 * INNER,
        /*hC*/ (long long)N2 * N1, /*bC*/ (long long)HEADS * N2 * N1,
        HEADS, 0.08838834764831845f);

    // softmax (fp32 -> fp16 P)
    softmax_kernel<<<B_SZ * HEADS * N2, 256>>>(S, P);

    // att = P @ v per (b,h): M=2048 N=128 K=2048 (half out)
    hgemm<__half><<<dim3(1, N2 / 128, B_SZ * HEADS), 256, GEMM_SMEM_BYTES>>>(
        P, vt, att, N1, N1, N1, INNER,
        /*hA*/ (long long)N2 * N1, /*bA*/ (long long)HEADS * N2 * N1,
        /*hB*/ (long long)DHEAD * N1, /*bB*/ (long long)INNER * N1,
        /*hC*/ DHEAD, /*bC*/ (long long)N2 * INNER,
        HEADS, 1.0f);

    // out = att @ w_out : M=4096 N=3072 K=2048 (float out)
    hgemm<float><<<dim3(DIM / 128, (B_SZ * N2) / 128, 1), 256,
                   GEMM_SMEM_BYTES>>>(
        att, woT, out, INNER, INNER, INNER, DIM,
        0, 0, 0, 0, 0, 0, 1, 1.0f);
}

// round 15
// speedup vs baseline: 1.6412x; 1.1540x over previous
#include <cuda_runtime.h>
#include <cuda_fp16.h>
#include <cstdint>

// ===========================================================================
// PerceiverAttentionCA — R15: identical to R13/R14 (broker timeouts).
// Flash-attention fusion: proj GEMMs (hgemm, validated R12) + fused
// S/softmax/PV kernel + out GEMM.
// ===========================================================================

#define B_SZ 2
#define N1 2048
#define N2 2048
#define DIM 3072
#define KV_DIM 2048
#define HEADS 16
#define DHEAD 128
#define INNER 2048

// ---------------- scratch (static device globals) ----------------
__device__ __align__(16) __half g_xn  [(size_t)B_SZ * N1 * KV_DIM];
__device__ __align__(16) __half g_ln  [(size_t)B_SZ * N2 * DIM];
__device__ __align__(16) __half g_q   [(size_t)B_SZ * N2 * INNER];
__device__ __align__(16) __half g_kv  [(size_t)B_SZ * N1 * 2 * INNER];
__device__ __align__(16) __half g_at  [(size_t)B_SZ * N2 * INNER];
__device__ __align__(16) __half g_wqT [(size_t)INNER * DIM];
__device__ __align__(16) __half g_wkvT[(size_t)2 * INNER * KV_DIM];
__device__ __align__(16) __half g_woT [(size_t)DIM * INNER];
__device__ __align__(16) __half g_vt  [(size_t)B_SZ * INNER * N1];

__device__ __forceinline__ uint32_t smem_u32(const void* p) {
    uint32_t a;
    asm("{ .reg .u64 t; cvta.to.shared.u64 t, %1; cvt.u32.u64 %0, t; }"
        : "=r"(a) : "l"(p));
    return a;
}

#define CP_ASYNC16(dst_u32, src_ptr) \
    asm volatile("cp.async.ca.shared.global [%0], [%1], 16;" \
                 :: "r"(dst_u32), "l"(src_ptr))
#define CP_COMMIT() asm volatile("cp.async.commit_group;")
#define CP_WAIT2()  asm volatile("cp.async.wait_group 2;")
#define CP_WAIT0()  asm volatile("cp.async.wait_group 0;")

__device__ __forceinline__ void ldsm_x4(uint32_t* r, uint32_t addr) {
    asm volatile("ldmatrix.sync.aligned.m8n8.x4.shared.b16 {%0,%1,%2,%3}, [%4];"
                 : "=r"(r[0]), "=r"(r[1]), "=r"(r[2]), "=r"(r[3]) : "r"(addr));
}
__device__ __forceinline__ void ldsm_x2(uint32_t* r, uint32_t addr) {
    asm volatile("ldmatrix.sync.aligned.m8n8.x2.shared.b16 {%0,%1}, [%2];"
                 : "=r"(r[0]), "=r"(r[1]) : "r"(addr));
}
__device__ __forceinline__ void mma_f16(float* d, const uint32_t* a,
                                        const uint32_t* b) {
    asm volatile(
        "mma.sync.aligned.m16n8k16.row.col.f32.f16.f16.f32 "
        "{%0,%1,%2,%3}, {%4,%5,%6,%7}, {%8,%9}, {%0,%1,%2,%3};"
        : "+f"(d[0]), "+f"(d[1]), "+f"(d[2]), "+f"(d[3])
        : "r"(a[0]), "r"(a[1]), "r"(a[2]), "r"(a[3]), "r"(b[0]), "r"(b[1]));
}
__device__ __forceinline__ uint32_t packh2(float a, float b) {
    __half2 h = __floats2half2_rn(a, b);
    return *(uint32_t*)&h;
}

// ---------------- hgemm smem swizzle (64B rows, BK=32) — validated R12 ----
__device__ __forceinline__ uint32_t swz(int row, int u) {
    return (uint32_t)(row * 64 + ((u ^ ((row >> 1) & 3)) << 4));
}
// ---------------- flash smem swizzle (256B rows, 16 units) ----------------
__device__ __forceinline__ uint32_t swz256(int row, int u) {
    return (uint32_t)(row * 256 + ((u ^ (row & 7)) << 4));
}

#define STAGE_BYTES 16384
#define GEMM_SMEM_BYTES (4 * STAGE_BYTES)

template <typename OutT>
__device__ __forceinline__ void store2(OutT* p, float x, float y);
template <>
__device__ __forceinline__ void store2<float>(float* p, float x, float y) {
    *(float2*)p = make_float2(x, y);
}
template <>
__device__ __forceinline__ void store2<__half>(__half* p, float x, float y) {
    *(__half2*)p = __floats2half2_rn(x, y);
}

// ======================= hgemm (unchanged from R12) ========================
template <typename OutT>
__global__ void __launch_bounds__(256, 2) hgemm(
    const __half* __restrict__ A, const __half* __restrict__ B,
    OutT* __restrict__ C,
    int K, int lda, int ldb, int ldc, float alpha)
{
    extern __shared__ char smem[];
    const uint32_t sbase = smem_u32(smem);
    const int tid = threadIdx.x;
    const int lid = tid & 31, wid = tid >> 5;
    const int wm = wid >> 2, wn = wid & 3;

    const int bm = blockIdx.y << 7, bn = blockIdx.x << 7;

    const int row = tid & 127;
    const int kb  = tid >> 7;
    const __half* srcA = A + (size_t)(bm + row) * lda + (kb << 4);
    const __half* srcB = B + (size_t)(bn + row) * ldb + (kb << 4);
    const uint32_t dA0 = swz(row, kb * 2);
    const uint32_t dA1 = swz(row, kb * 2 + 1);

    const int S = K >> 5;

    #pragma unroll
    for (int st = 0; st < 3; st++) {
        if (st < S) {
            const uint32_t d = sbase + (st & 3) * STAGE_BYTES;
            const __half* a = srcA + (size_t)st * 32;
            const __half* b = srcB + (size_t)st * 32;
            CP_ASYNC16(d + dA0, a);
            CP_ASYNC16(d + dA1, a + 8);
            CP_ASYNC16(d + 8192 + dA0, b);
            CP_ASYNC16(d + 8192 + dA1, b + 8);
        }
        CP_COMMIT();
    }

    float acc[4][4][4];
    #pragma unroll
    for (int i = 0; i < 4; i++)
        #pragma unroll
        for (int j = 0; j < 4; j++)
            #pragma unroll
            for (int r = 0; r < 4; r++) acc[i][j][r] = 0.f;

    uint32_t offFA0[4], offFA1[4], offFB0[4], offFB1[4];
    {
        const int ua = lid >> 4;
        const int ub = (lid >> 3) & 1;
        #pragma unroll
        for (int mt = 0; mt < 4; mt++) {
            int r = (wm << 6) + (mt << 4) + (((lid >> 3) & 1) << 3) + (lid & 7);
            offFA0[mt] = swz(r, 0 + ua);
            offFA1[mt] = swz(r, 2 + ua);
        }
        #pragma unroll
        for (int nt = 0; nt < 4; nt++) {
            int r = (wn << 5) + (nt << 3) + (lid & 7);
            offFB0[nt] = swz(r, 0 + ub);
            offFB1[nt] = swz(r, 2 + ub);
        }
    }

    for (int s = 0; s < S; s++) {
        CP_WAIT2();
        __syncthreads();
        if (s + 3 < S) {
            const int st = s + 3;
            const uint32_t d = sbase + (st & 3) * STAGE_BYTES;
            const __half* a = srcA + (size_t)st * 32;
            const __half* b = srcB + (size_t)st * 32;
            CP_ASYNC16(d + dA0, a);
            CP_ASYNC16(d + dA1, a + 8);
            CP_ASYNC16(d + 8192 + dA0, b);
            CP_ASYNC16(d + 8192 + dA1, b + 8);
        }
        CP_COMMIT();

        const uint32_t sA = sbase + (s & 3) * STAGE_BYTES;
        const uint32_t sB = sA + 8192;
        #pragma unroll
        for (int ks = 0; ks < 2; ks++) {
            uint32_t Af[4][4], Bf[4][2];
            #pragma unroll
            for (int mt = 0; mt < 4; mt++)
                ldsm_x4(Af[mt], sA + (ks ? offFA1[mt] : offFA0[mt]));
            #pragma unroll
            for (int nt = 0; nt < 4; nt++)
                ldsm_x2(Bf[nt], sB + (ks ? offFB1[nt] : offFB0[nt]));
            #pragma unroll
            for (int mt = 0; mt < 4; mt++)
                #pragma unroll
                for (int nt = 0; nt < 4; nt++)
                    mma_f16(acc[mt][nt], Af[mt], Bf[nt]);
        }
    }

    #pragma unroll
    for (int mt = 0; mt < 4; mt++) {
        #pragma unroll
        for (int nt = 0; nt < 4; nt++) {
            int r = bm + (wm << 6) + (mt << 4) + (lid >> 2);
            int c = bn + (wn << 5) + (nt << 3) + ((lid & 3) << 1);
            store2<OutT>(C + (size_t)r * ldc + c,
                         acc[mt][nt][0] * alpha, acc[mt][nt][1] * alpha);
            store2<OutT>(C + (size_t)(r + 8) * ldc + c,
                         acc[mt][nt][2] * alpha, acc[mt][nt][3] * alpha);
        }
    }
}

// ======================= fused flash attention =============================
// grid (16 q-blocks, 32 bh). q[128x128] resident; loop 16 key-tiles of 128.
#define ATT_Q  0
#define ATT_K0 32768
#define ATT_K1 65536
#define ATT_V0 98304
#define ATT_V1 131072
#define ATT_SMEM 163840

__global__ void __launch_bounds__(256, 1) flash_kernel(
    const __half* __restrict__ Q, const __half* __restrict__ KV,
    const __half* __restrict__ VT, __half* __restrict__ O)
{
    extern __shared__ char smem[];
    const uint32_t sb = smem_u32(smem);
    const int tid = threadIdx.x, lid = tid & 31, wid = tid >> 5;
    const int z = blockIdx.y, b = z >> 4, h = z & 15;
    const int bq = blockIdx.x;

    const __half* qbase = Q  + ((size_t)b * N2 + bq * 128) * INNER + h * DHEAD;
    const __half* kbase = KV + (size_t)b * N1 * 2 * INNER + h * DHEAD;
    const __half* vbase = VT + (size_t)b * INNER * N1 + (size_t)h * DHEAD * N1;
    __half* obase = O + ((size_t)b * N2 + bq * 128) * INNER + h * DHEAD;

    const int srow = tid & 127;
    const int hu0  = (tid >> 7) << 3;      // units 0..7 or 8..15

    // prologue: q + k0 + v0 (one group)
    {
        const __half* qs = qbase + (size_t)srow * INNER + hu0 * 8;
        const __half* ks = kbase + (size_t)srow * (2 * INNER) + hu0 * 8;
        const __half* vs = vbase + (size_t)srow * N1 + hu0 * 8;
        #pragma unroll
        for (int i = 0; i < 8; i++) {
            CP_ASYNC16(sb + ATT_Q  + swz256(srow, hu0 + i), qs + i * 8);
            CP_ASYNC16(sb + ATT_K0 + swz256(srow, hu0 + i), ks + i * 8);
            CP_ASYNC16(sb + ATT_V0 + swz256(srow, hu0 + i), vs + i * 8);
        }
        CP_COMMIT();
    }

    float o_[16][4];
    #pragma unroll
    for (int d = 0; d < 16; d++)
        #pragma unroll
        for (int r = 0; r < 4; r++) o_[d][r] = 0.f;
    float mA = -1e30f, mB = -1e30f, lA = 0.f, lB = 0.f;

    uint32_t qf[8][4];
    const int rk = lid & 7;            // B-frag row-within-tile
    const int ub = (lid >> 3) & 1;     // B-frag unit-within-pair
    const float SCL = 0.08838834764831845f;   // 1/sqrt(128)

    for (int t = 0; t < 16; t++) {
        CP_WAIT0();
        __syncthreads();

        if (t == 0) {
            // q fragments (register-resident for the whole kernel)
            const int r = (wid << 4) + (((lid >> 3) & 1) << 3) + (lid & 7);
            #pragma unroll
            for (int ks = 0; ks < 8; ks++)
                ldsm_x4(qf[ks], sb + ATT_Q + swz256(r, ks * 2 + (lid >> 4)));
        }

        // prefetch next tile into other buffer
        if (t + 1 < 16) {
            const int r2 = (t + 1) * 128 + srow;
            const __half* ks = kbase + (size_t)r2 * (2 * INNER) + hu0 * 8;
            const __half* vs = vbase + (size_t)srow * N1 + (t + 1) * 128 + hu0 * 8;
            const uint32_t kd = sb + (((t + 1) & 1) ? ATT_K1 : ATT_K0);
            const uint32_t vd = sb + (((t + 1) & 1) ? ATT_V1 : ATT_V0);
            #pragma unroll
            for (int i = 0; i < 8; i++) {
                CP_ASYNC16(kd + swz256(srow, hu0 + i), ks + i * 8);
                CP_ASYNC16(vd + swz256(srow, hu0 + i), vs + i * 8);
            }
        }
        CP_COMMIT();

        const uint32_t kbuf = sb + ((t & 1) ? ATT_K1 : ATT_K0);
        const uint32_t vbuf = sb + ((t & 1) ? ATT_V1 : ATT_V0);

        // S = q @ k^T for this warp's 16 rows x 128 keys
        float s[16][4];
        #pragma unroll
        for (int nt = 0; nt < 16; nt++)
            #pragma unroll
            for (int r = 0; r < 4; r++) s[nt][r] = 0.f;
        #pragma unroll
        for (int ks = 0; ks < 8; ks++) {
            #pragma unroll
            for (int nt = 0; nt < 16; nt++) {
                uint32_t kf[2];
                ldsm_x2(kf, kbuf + swz256(nt * 8 + rk, ks * 2 + ub));
                mma_f16(s[nt], qf[ks], kf);
            }
        }

        // online softmax (rows rA = lid>>2, rB = rA+8)
        float mxA = -1e30f, mxB = -1e30f;
        #pragma unroll
        for (int nt = 0; nt < 16; nt++) {
            s[nt][0] *= SCL; s[nt][1] *= SCL;
            s[nt][2] *= SCL; s[nt][3] *= SCL;
            mxA = fmaxf(mxA, fmaxf(s[nt][0], s[nt][1]));
            mxB = fmaxf(mxB, fmaxf(s[nt][2], s[nt][3]));
        }
        mxA = fmaxf(mxA, __shfl_xor_sync(0xffffffffu, mxA, 1));
        mxA = fmaxf(mxA, __shfl_xor_sync(0xffffffffu, mxA, 2));
        mxB = fmaxf(mxB, __shfl_xor_sync(0xffffffffu, mxB, 1));
        mxB = fmaxf(mxB, __shfl_xor_sync(0xffffffffu, mxB, 2));

        const float mnA = fmaxf(mA, mxA), mnB = fmaxf(mB, mxB);
        const float cA = __expf(mA - mnA), cB = __expf(mB - mnB);
        mA = mnA; mB = mnB;

        float sA = 0.f, sB = 0.f;
        #pragma unroll
        for (int nt = 0; nt < 16; nt++) {
            s[nt][0] = __expf(s[nt][0] - mnA);
            s[nt][1] = __expf(s[nt][1] - mnA);
            s[nt][2] = __expf(s[nt][2] - mnB);
            s[nt][3] = __expf(s[nt][3] - mnB);
            sA += s[nt][0] + s[nt][1];
            sB += s[nt][2] + s[nt][3];
        }
        sA += __shfl_xor_sync(0xffffffffu, sA, 1);
        sA += __shfl_xor_sync(0xffffffffu, sA, 2);
        sB += __shfl_xor_sync(0xffffffffu, sB, 1);
        sB += __shfl_xor_sync(0xffffffffu, sB, 2);
        lA = lA * cA + sA;
        lB = lB * cB + sB;

        #pragma unroll
        for (int d = 0; d < 16; d++) {
            o_[d][0] *= cA; o_[d][1] *= cA;
            o_[d][2] *= cB; o_[d][3] *= cB;
        }

        // pack P into PV A-fragments (C-layout == A-layout after half2 pack)
        uint32_t pf[8][4];
        #pragma unroll
        for (int j = 0; j < 8; j++) {
            pf[j][0] = packh2(s[2 * j][0],     s[2 * j][1]);
            pf[j][1] = packh2(s[2 * j][2],     s[2 * j][3]);
            pf[j][2] = packh2(s[2 * j + 1][0], s[2 * j + 1][1]);
            pf[j][3] = packh2(s[2 * j + 1][2], s[2 * j + 1][3]);
        }

        // o += P @ v  (vt is d-major, keys contiguous -> K-major B)
        #pragma unroll
        for (int j = 0; j < 8; j++) {
            #pragma unroll
            for (int d = 0; d < 16; d++) {
                uint32_t vf[2];
                ldsm_x2(vf, vbuf + swz256(d * 8 + rk, j * 2 + ub));
                mma_f16(o_[d], pf[j], vf);
            }
        }
    }

    // epilogue
    const float iA = 1.f / lA, iB = 1.f / lB;
    const int rA = (wid << 4) + (lid >> 2);
    #pragma unroll
    for (int d = 0; d < 16; d++) {
        const int c = d * 8 + ((lid & 3) << 1);
        *(__half2*)(obase + (size_t)rA * INNER + c) =
            __floats2half2_rn(o_[d][0] * iA, o_[d][1] * iA);
        *(__half2*)(obase + (size_t)(rA + 8) * INNER + c) =
            __floats2half2_rn(o_[d][2] * iB, o_[d][3] * iB);
    }
}

// ---------------------------------------------------------------------------
// LayerNorm: fp32 in, fp16 out
// ---------------------------------------------------------------------------
__global__ void __launch_bounds__(256) ln_kernel(
    const float* __restrict__ x, const float* __restrict__ gam,
    const float* __restrict__ bet, __half* __restrict__ out, int cols)
{
    const int row = blockIdx.x;
    const float* xr = x + (size_t)row * cols;
    __half* orow = out + (size_t)row * cols;

    float s = 0.f, s2 = 0.f;
    for (int i = threadIdx.x; i < cols; i += blockDim.x) {
        float v = xr[i]; s += v; s2 += v * v;
    }
    __shared__ float sm0[8], sm1[8];
    #pragma unroll
    for (int o = 16; o > 0; o >>= 1) {
        s  += __shfl_down_sync(0xffffffffu, s,  o);
        s2 += __shfl_down_sync(0xffffffffu, s2, o);
    }
    int w = threadIdx.x >> 5, l = threadIdx.x & 31;
    if (l == 0) { sm0[w] = s; sm1[w] = s2; }
    __syncthreads();
    if (threadIdx.x == 0) {
        float ts = 0.f, t2 = 0.f;
        #pragma unroll
        for (int i = 0; i < 8; i++) { ts += sm0[i]; t2 += sm1[i]; }
        float mu  = ts / (float)cols;
        float var = t2 / (float)cols - mu * mu;
        sm0[0] = mu; sm1[0] = rsqrtf(var + 1e-5f);
    }
    __syncthreads();
    float mu = sm0[0], rs = sm1[0];
    for (int i = threadIdx.x; i < cols; i += blockDim.x) {
        float v = xr[i];
        orow[i] = __float2half((v - mu) * rs * gam[i] + bet[i]);
    }
}

// ---------------------------------------------------------------------------
// Batched 32x32 tiled transpose: Tin in -> half out
// ---------------------------------------------------------------------------
template <typename Tin>
__global__ void transpose_kernel(
    const Tin* __restrict__ in, __half* __restrict__ out,
    int ldi, int ldo,
    long long hI, long long bI, long long hO, long long bO, int nheads)
{
    __shared__ __half t[32][34];
    const int z = blockIdx.z;
    const int bb = z / nheads, hh = z % nheads;
    in  += (size_t)bb * bI + (size_t)hh * hI;
    out += (size_t)bb * bO + (size_t)hh * hO;
    int x = blockIdx.x * 32 + threadIdx.x;
    int y = blockIdx.y * 32 + threadIdx.y;
    #pragma unroll
    for (int j = 0; j < 32; j += 8)
        t[threadIdx.y + j][threadIdx.x] =
            __float2half((float)in[(size_t)(y + j) * ldi + x]);
    __syncthreads();
    int x2 = blockIdx.y * 32 + threadIdx.x;
    int y2 = blockIdx.x * 32 + threadIdx.y;
    #pragma unroll
    for (int j = 0; j < 32; j += 8)
        out[(size_t)(y2 + j) * ldo + x2] = t[threadIdx.x][threadIdx.y + j];
}

// ---------------------------------------------------------------------------
extern "C" void kernel_launch(void* const* d_in, const int* in_sizes, int n_in,
                              void* d_out, int out_size)
{
    const float* x      = (const float*)d_in[0];
    const float* lat    = (const float*)d_in[1];
    const float* w_q    = (const float*)d_in[2];
    const float* w_kv   = (const float*)d_in[3];
    const float* w_out  = (const float*)d_in[4];
    const float* ln1_g  = (const float*)d_in[5];
    const float* ln1_b  = (const float*)d_in[6];
    const float* ln2_g  = (const float*)d_in[7];
    const float* ln2_b  = (const float*)d_in[8];
    float* out = (float*)d_out;

    __half *xn, *ln, *q, *kv, *att, *wqT, *wkvT, *woT, *vt;
    cudaGetSymbolAddress((void**)&xn,   g_xn);
    cudaGetSymbolAddress((void**)&ln,   g_ln);
    cudaGetSymbolAddress((void**)&q,    g_q);
    cudaGetSymbolAddress((void**)&kv,   g_kv);
    cudaGetSymbolAddress((void**)&att,  g_at);
    cudaGetSymbolAddress((void**)&wqT,  g_wqT);
    cudaGetSymbolAddress((void**)&wkvT, g_wkvT);
    cudaGetSymbolAddress((void**)&woT,  g_woT);
    cudaGetSymbolAddress((void**)&vt,   g_vt);

    cudaFuncSetAttribute(hgemm<float>,
        cudaFuncAttributeMaxDynamicSharedMemorySize, GEMM_SMEM_BYTES);
    cudaFuncSetAttribute(hgemm<__half>,
        cudaFuncAttributeMaxDynamicSharedMemorySize, GEMM_SMEM_BYTES);
    cudaFuncSetAttribute(flash_kernel,
        cudaFuncAttributeMaxDynamicSharedMemorySize, ATT_SMEM);

    const dim3 tb(32, 8);

    // LayerNorms (fp32 -> fp16)
    ln_kernel<<<B_SZ * N1, 256>>>(x,   ln1_g, ln1_b, xn, KV_DIM);
    ln_kernel<<<B_SZ * N2, 256>>>(lat, ln2_g, ln2_b, ln, DIM);

    // weight transposes (fp32 -> fp16, K-major)
    transpose_kernel<float><<<dim3(INNER / 32, DIM / 32, 1), tb>>>(
        w_q, wqT, INNER, DIM, 0, 0, 0, 0, 1);
    transpose_kernel<float><<<dim3((2 * INNER) / 32, KV_DIM / 32, 1), tb>>>(
        w_kv, wkvT, 2 * INNER, KV_DIM, 0, 0, 0, 0, 1);
    transpose_kernel<float><<<dim3(DIM / 32, INNER / 32, 1), tb>>>(
        w_out, woT, DIM, INNER, 0, 0, 0, 0, 1);

    // q = ln @ w_q : M=4096 N=2048 K=3072 (half out)
    hgemm<__half><<<dim3(INNER / 128, (B_SZ * N2) / 128), 256,
                    GEMM_SMEM_BYTES>>>(ln, wqT, q, DIM, DIM, DIM, INNER, 1.0f);

    // kv = xn @ w_kv : M=4096 N=4096 K=2048 (half out)
    hgemm<__half><<<dim3((2 * INNER) / 128, (B_SZ * N1) / 128), 256,
                    GEMM_SMEM_BYTES>>>(xn, wkvT, kv, KV_DIM, KV_DIM, KV_DIM,
                                       2 * INNER, 1.0f);

    // v^T per (b,h): vt[b][h][d][n1]
    transpose_kernel<__half><<<dim3(DHEAD / 32, N1 / 32, B_SZ * HEADS), tb>>>(
        kv + INNER, vt, 2 * INNER, N1,
        /*hI*/ DHEAD, /*bI*/ (long long)N1 * 2 * INNER,
        /*hO*/ (long long)DHEAD * N1, /*bO*/ (long long)INNER * N1, HEADS);

    // fused attention: att = softmax(q k^T / sqrt(d)) v   (half out)
    flash_kernel<<<dim3(N2 / 128, B_SZ * HEADS), 256, ATT_SMEM>>>(
        q, kv, vt, att);

    // out = att @ w_out : M=4096 N=3072 K=2048 (float out)
    hgemm<float><<<dim3(DIM / 128, (B_SZ * N2) / 128), 256,
                   GEMM_SMEM_BYTES>>>(att, woT, out, INNER, INNER, INNER,
                                      DIM, 1.0f);
}